// round 15
// baseline (speedup 1.0000x reference)
#include <cuda_runtime.h>
#include <cuda_fp16.h>
#include <cstdint>

// Problem constants
#define BATCH 2
#define SEQ   2048
#define DIM   1024
#define HEADS 16
#define HD    64
#define NTOK  (BATCH*SEQ)   // 4096

// ---------------------------------------------------------------------------
// Scratch (__device__ globals; allocation-free rule)
// ---------------------------------------------------------------------------
__device__ __half g_xhi[(size_t)NTOK * DIM];
__device__ __half g_wqh[(size_t)3 * DIM * DIM];
__device__ __half g_woh[(size_t)DIM * DIM];
__device__ __half g_qhi[(size_t)NTOK * DIM];        // Q (pre-scaled) hi
__device__ __half g_khi[(size_t)NTOK * DIM];        // K hi
__device__ __half g_vhi[(size_t)NTOK * DIM];        // V hi
__device__ __half g_ahi[(size_t)NTOK * DIM];        // attn out hi

// ---------------------------------------------------------------------------
// PTX helpers (baseline sm_100-safe)
// ---------------------------------------------------------------------------
__device__ __forceinline__ uint32_t smem_u32(const void* p) {
    uint32_t a;
    asm("{ .reg .u64 t; cvta.to.shared.u64 t, %1; cvt.u32.u64 %0, t; }" : "=r"(a) : "l"(p));
    return a;
}
#define SWZ128(off) ((off) ^ (((off) >> 3) & 0x70))

#define CP_ASYNC16(saddr, gptr) \
    asm volatile("cp.async.cg.shared.global [%0], [%1], 16;\n" :: "r"(saddr), "l"(gptr))
#define CP_COMMIT() asm volatile("cp.async.commit_group;\n" ::: "memory")
#define CP_WAIT(N)  asm volatile("cp.async.wait_group %0;\n" :: "n"(N) : "memory")

#define LDSM_X4(r0, r1, r2, r3, addr) \
    asm volatile("ldmatrix.sync.aligned.m8n8.x4.shared.b16 {%0,%1,%2,%3}, [%4];" \
                 : "=r"(r0), "=r"(r1), "=r"(r2), "=r"(r3) : "r"(addr))
#define LDSM_X4_T(r0, r1, r2, r3, addr) \
    asm volatile("ldmatrix.sync.aligned.m8n8.x4.trans.shared.b16 {%0,%1,%2,%3}, [%4];" \
                 : "=r"(r0), "=r"(r1), "=r"(r2), "=r"(r3) : "r"(addr))

#define MMAF16(c, a, b0, b1) \
    asm volatile("mma.sync.aligned.m16n8k16.row.col.f32.f16.f16.f32 " \
                 "{%0,%1,%2,%3}, {%4,%5,%6,%7}, {%8,%9}, {%0,%1,%2,%3};" \
                 : "+f"((c)[0]), "+f"((c)[1]), "+f"((c)[2]), "+f"((c)[3]) \
                 : "r"((a)[0]), "r"((a)[1]), "r"((a)[2]), "r"((a)[3]), \
                   "r"(b0), "r"(b1))

__device__ __forceinline__ uint32_t pack_h2(float a, float b) {
    __half2 v(__float2half(a), __float2half(b));
    return *(uint32_t*)&v;
}

// ---------------------------------------------------------------------------
// fused convert kernel: x, Wqkv, Wo -> fp16
// ---------------------------------------------------------------------------
#define N4_X  (NTOK * DIM / 4)
#define N4_WQ (3 * DIM * DIM / 4)
#define N4_WO (DIM * DIM / 4)

__global__ void split_all(const float* __restrict__ x,  __half* __restrict__ xhi,
                          const float* __restrict__ wq, __half* __restrict__ wqh,
                          const float* __restrict__ wo, __half* __restrict__ woh)
{
    int i = blockIdx.x * blockDim.x + threadIdx.x;
    const float* src; __half* dst;
    if (i < N4_X) { src = x; dst = xhi; }
    else if (i < N4_X + N4_WQ) { i -= N4_X; src = wq; dst = wqh; }
    else if (i < N4_X + N4_WQ + N4_WO) { i -= N4_X + N4_WQ; src = wo; dst = woh; }
    else return;
    float4 v = ((const float4*)src)[i];
    __half2* hp = (__half2*)(dst + (size_t)i * 4);
    hp[0] = __half2(__float2half(v.x), __float2half(v.y));
    hp[1] = __half2(__float2half(v.z), __float2half(v.w));
}

// ---------------------------------------------------------------------------
// 1-term fp16 GEMM: CTA 128x128, 128 threads (4 warps x 64x64), BK=64, 3 stages.
// One __syncthreads per k-iteration (canonical multi-stage pattern).
// ---------------------------------------------------------------------------
#define BM 128
#define BN 128
#define BKG 64
#define AG_BYTES (BM * BKG * 2)            // 16384
#define BG_BYTES (BN * BKG * 2)            // 16384
#define STAGE_B (AG_BYTES + BG_BYTES)      // 32768
#define GEMM_SMEM (3 * STAGE_B)            // 98304

#define GEMM_MAINLOOP_1T(Ahi, Bh, K)                                                \
    extern __shared__ __align__(1024) char smem[];                                  \
    const uint32_t sbase = smem_u32(smem);                                          \
    const int tid  = threadIdx.x;                                                   \
    const int wid  = tid >> 5;                                                      \
    const int lane = tid & 31;                                                      \
    const int m0 = blockIdx.y * BM;                                                 \
    const int n0 = blockIdx.x * BN;                                                 \
    const int m_off = (wid & 1) * 64;                                               \
    const int n_off = (wid >> 1) * 64;                                              \
    const __half* aSrc = Ahi + (size_t)m0 * K;                                      \
    const __half* bSrc = Bh + (size_t)n0 * K;                                       \
    const int NIT = K / BKG;                                                        \
    auto load_stage = [&](int sbuf, int k0) {                                       \
        uint32_t stg = sbase + sbuf * STAGE_B;                                      \
        _Pragma("unroll")                                                           \
        for (int r = 0; r < 8; r++) {                                               \
            int idx = r * 128 + tid;                                                \
            int row = idx >> 3, cch = idx & 7;                                      \
            uint32_t soff = SWZ128((uint32_t)(row * 128 + cch * 16));               \
            CP_ASYNC16(stg + soff, aSrc + k0 + (size_t)row * K + cch * 8);          \
        }                                                                           \
        _Pragma("unroll")                                                           \
        for (int r = 0; r < 8; r++) {                                               \
            int idx = r * 128 + tid;                                                \
            int row = idx >> 3, cch = idx & 7;                                      \
            uint32_t soff = SWZ128((uint32_t)(row * 128 + cch * 16));               \
            CP_ASYNC16(stg + AG_BYTES + soff, bSrc + k0 + (size_t)row * K + cch * 8);\
        }                                                                           \
    };                                                                              \
    float c[4][8][4];                                                               \
    _Pragma("unroll")                                                               \
    for (int i = 0; i < 4; i++)                                                     \
        _Pragma("unroll")                                                           \
        for (int j = 0; j < 8; j++)                                                 \
            _Pragma("unroll")                                                       \
            for (int t = 0; t < 4; t++) c[i][j][t] = 0.f;                           \
    load_stage(0, 0); CP_COMMIT();                                                  \
    load_stage(1, BKG); CP_COMMIT();                                                \
    const int lr = lane & 15;                                                       \
    const int lk = lane >> 4;                                                       \
    int sbuf = 0;                                                                   \
    for (int it = 0; it < NIT; it++) {                                              \
        if (it + 1 < NIT) { CP_WAIT(1); } else { CP_WAIT(0); }                      \
        __syncthreads();                                                            \
        if (it + 2 < NIT) { load_stage((sbuf + 2) % 3, (it + 2) * BKG); CP_COMMIT(); } \
        uint32_t stg  = sbase + sbuf * STAGE_B;                                     \
        uint32_t aHiB = stg;                                                        \
        uint32_t bHiB = stg + AG_BYTES;                                             \
        _Pragma("unroll")                                                           \
        for (int ks = 0; ks < 4; ks++) {                                            \
            uint32_t ahi[4][4];                                                     \
            _Pragma("unroll")                                                       \
            for (int mi = 0; mi < 4; mi++) {                                        \
                uint32_t sw = SWZ128((uint32_t)((m_off + mi * 16 + lr) * 128 + ks * 32 + lk * 16)); \
                LDSM_X4(ahi[mi][0], ahi[mi][1], ahi[mi][2], ahi[mi][3], aHiB + sw); \
            }                                                                       \
            _Pragma("unroll")                                                       \
            for (int ng = 0; ng < 4; ng++) {                                        \
                uint32_t sw = SWZ128((uint32_t)((n_off + ng * 16 + lr) * 128 + ks * 32 + lk * 16)); \
                uint32_t bh0, bh1, bh2, bh3;                                        \
                LDSM_X4(bh0, bh1, bh2, bh3, bHiB + sw);                             \
                _Pragma("unroll")                                                   \
                for (int mi = 0; mi < 4; mi++) {                                    \
                    MMAF16(c[mi][ng*2+0], ahi[mi], bh0, bh2);                       \
                    MMAF16(c[mi][ng*2+1], ahi[mi], bh1, bh3);                       \
                }                                                                   \
            }                                                                       \
        }                                                                           \
        sbuf = (sbuf + 1) % 3;                                                      \
    }                                                                               \
    const int cr = lane >> 2;                                                       \
    const int cc = (lane & 3) * 2;

// ---------------------------------------------------------------------------
// GEMM1: qkv projection, epilogue -> Q(hi, scaled), K(hi), V(hi)
// ---------------------------------------------------------------------------
__global__ __launch_bounds__(128, 2)
void gemm_qkv(const __half* __restrict__ Ahi, const __half* __restrict__ Bh,
              __half* __restrict__ qhi, __half* __restrict__ khi,
              __half* __restrict__ vhi)
{
    GEMM_MAINLOOP_1T(Ahi, Bh, DIM)

    const int seg  = n0 >> 10;           // 0=Q, 1=K, 2=V
    const int col0 = (n0 & 1023) + n_off;
    __half* dst = (seg == 0) ? qhi : (seg == 1) ? khi : vhi;
    const float sc = (seg == 0) ? 0.125f : 1.0f;
#pragma unroll
    for (int mi = 0; mi < 4; mi++) {
        int r0 = m0 + m_off + mi * 16 + cr;
#pragma unroll
        for (int j = 0; j < 8; j++) {
            int col = col0 + j * 8 + cc;
            *(uint32_t*)(dst + (size_t)r0 * DIM + col) =
                pack_h2(c[mi][j][0] * sc, c[mi][j][1] * sc);
            *(uint32_t*)(dst + (size_t)(r0 + 8) * DIM + col) =
                pack_h2(c[mi][j][2] * sc, c[mi][j][3] * sc);
        }
    }
}

// ---------------------------------------------------------------------------
// GEMM2: out projection, fp32 out
// ---------------------------------------------------------------------------
__global__ __launch_bounds__(128, 2)
void gemm_out(const __half* __restrict__ Ahi, const __half* __restrict__ Bh,
              float* __restrict__ C)
{
    GEMM_MAINLOOP_1T(Ahi, Bh, DIM)

#pragma unroll
    for (int mi = 0; mi < 4; mi++) {
        int r0 = m0 + m_off + mi * 16 + cr;
#pragma unroll
        for (int j = 0; j < 8; j++) {
            int col = n0 + n_off + j * 8 + cc;
            *(float2*)(C + (size_t)r0 * DIM + col)       = make_float2(c[mi][j][0], c[mi][j][1]);
            *(float2*)(C + (size_t)(r0 + 8) * DIM + col) = make_float2(c[mi][j][2], c[mi][j][3]);
        }
    }
}

// ---------------------------------------------------------------------------
// Flash attention: S = Qhi·Khi; PV = Phi·Vhi. ALiBi + causal.
// 3-stage K/V cp.async pipeline, ONE __syncthreads per key-tile.
// Fully-masked warps skip the diagonal tile's compute.
// smem: Q 16384, KV stages 16384x3 at 16384, P 16384 at 65536 -> 81920.
// ---------------------------------------------------------------------------
#define ATT_SMEM 81920
#define Q_HI 0
#define STG0 16384
#define P_HI 65536

__global__ __launch_bounds__(256, 2)
void attn_mma(const __half* __restrict__ qhi,
              const __half* __restrict__ khi, const __half* __restrict__ vhi,
              __half* __restrict__ out_hi)
{
    extern __shared__ __align__(1024) char smem[];
    const uint32_t sbase = smem_u32(smem);
    const int tid  = threadIdx.x;
    const int wid  = tid >> 5;
    const int lane = tid & 31;
    const int lr   = lane & 15;
    const int lk   = lane >> 4;

    const int qt = (int)(gridDim.x - 1 - blockIdx.x);   // largest tiles first
    const int bh = blockIdx.y;
    const int b  = bh >> 4;
    const int h  = bh & 15;
    const int q0 = qt * 128;

    const float slope = exp2f(-0.5f * (float)(h + 1));

    const __half* qh_base = qhi + (size_t)(b * SEQ) * DIM + h * HD;
    const __half* kh_base = khi + (size_t)(b * SEQ) * DIM + h * HD;
    const __half* vh_base = vhi + (size_t)(b * SEQ) * DIM + h * HD;

    // ---- issue Q tile loads (group 0, with KV tile 0) ----
#pragma unroll
    for (int r = 0; r < 4; r++) {
        int idx = r * 256 + tid;
        int row = idx >> 3;
        int ch  = idx & 7;
        uint32_t soff = SWZ128((uint32_t)(row * 128 + ch * 16));
        CP_ASYNC16(sbase + Q_HI + soff, qh_base + (size_t)(q0 + row) * DIM + ch * 8);
    }

    const int nkt = 2 * qt + 2;

    auto issue_kv = [&](int kt, int s) {
        uint32_t stg = sbase + STG0 + s * 16384;
        int k0 = kt * 64;
#pragma unroll
        for (int r = 0; r < 2; r++) {
            int idx = r * 256 + tid;
            int row = idx >> 3;
            int ch  = idx & 7;
            uint32_t soff = SWZ128((uint32_t)(row * 128 + ch * 16));
            CP_ASYNC16(stg + soff,        kh_base + (size_t)(k0 + row) * DIM + ch * 8);
            CP_ASYNC16(stg + 8192 + soff, vh_base + (size_t)(k0 + row) * DIM + ch * 8);
        }
    };

    issue_kv(0, 0);
    CP_COMMIT();
    issue_kv(1, 1);      // nkt >= 2 always
    CP_COMMIT();

    float cs[8][4];
    float co[8][4];
#pragma unroll
    for (int j = 0; j < 8; j++)
#pragma unroll
        for (int t = 0; t < 4; t++) co[j][t] = 0.f;

    float m0v = -1e30f, m1v = -1e30f, l0v = 0.f, l1v = 0.f;

    const int r0 = lane >> 2;
    const int ccol = (lane & 3) * 2;
    const int gi0 = q0 + wid * 16 + r0;
    const int gi1 = gi0 + 8;

    for (int kt = 0; kt < nkt; kt++) {
        const int s = kt % 3;
        const int k0 = kt * 64;
        const uint32_t stgo = STG0 + s * 16384;

        if (kt + 1 < nkt) { CP_WAIT(1); } else { CP_WAIT(0); }
        __syncthreads();
        if (kt + 2 < nkt) { issue_kv(kt + 2, (kt + 2) % 3); CP_COMMIT(); }

        // Fully-masked warps (diagonal tile, query rows < tile keys) skip.
        if (kt == nkt - 1 && wid < 4) continue;

        // ---- S = Q K^T ----
#pragma unroll
        for (int j = 0; j < 8; j++)
#pragma unroll
            for (int t = 0; t < 4; t++) cs[j][t] = 0.f;

        uint32_t kHiB = sbase + stgo;
#pragma unroll
        for (int ks = 0; ks < 4; ks++) {
            uint32_t qoff = SWZ128((uint32_t)((wid * 16 + lr) * 128 + ks * 32 + lk * 16));
            uint32_t ahi[4];
            LDSM_X4(ahi[0], ahi[1], ahi[2], ahi[3], sbase + Q_HI + qoff);
#pragma unroll
            for (int ng = 0; ng < 4; ng++) {
                uint32_t boff = SWZ128((uint32_t)((ng * 16 + lr) * 128 + ks * 32 + lk * 16));
                uint32_t bh0, bh1, bh2, bh3;
                LDSM_X4(bh0, bh1, bh2, bh3, kHiB + boff);
                MMAF16(cs[ng*2+0], ahi, bh0, bh2);
                MMAF16(cs[ng*2+1], ahi, bh1, bh3);
            }
        }

        // ---- ALiBi + causal mask ----
#pragma unroll
        for (int nb = 0; nb < 8; nb++) {
#pragma unroll
            for (int cidx = 0; cidx < 2; cidx++) {
                int gj = k0 + nb * 8 + ccol + cidx;
                float rel0 = slope * (float)(gj - gi0);
                float rel1 = slope * (float)(gj - gi1);
                cs[nb][cidx]     = (gj > gi0) ? -1e30f : cs[nb][cidx]     - rel0;
                cs[nb][2 + cidx] = (gj > gi1) ? -1e30f : cs[nb][2 + cidx] - rel1;
            }
        }

        // ---- online softmax ----
        float mx0 = -1e30f, mx1 = -1e30f;
#pragma unroll
        for (int nb = 0; nb < 8; nb++) {
            mx0 = fmaxf(mx0, fmaxf(cs[nb][0], cs[nb][1]));
            mx1 = fmaxf(mx1, fmaxf(cs[nb][2], cs[nb][3]));
        }
        mx0 = fmaxf(mx0, __shfl_xor_sync(0xffffffff, mx0, 1));
        mx0 = fmaxf(mx0, __shfl_xor_sync(0xffffffff, mx0, 2));
        mx1 = fmaxf(mx1, __shfl_xor_sync(0xffffffff, mx1, 1));
        mx1 = fmaxf(mx1, __shfl_xor_sync(0xffffffff, mx1, 2));

        float mn0 = fmaxf(m0v, mx0), mn1 = fmaxf(m1v, mx1);
        float corr0 = __expf(m0v - mn0), corr1 = __expf(m1v - mn1);
        m0v = mn0; m1v = mn1;

        float sum0 = 0.f, sum1 = 0.f;
        const int prow0 = wid * 16 + r0;
#pragma unroll
        for (int nb = 0; nb < 8; nb++) {
            float p00 = __expf(cs[nb][0] - mn0);
            float p01 = __expf(cs[nb][1] - mn0);
            float p10 = __expf(cs[nb][2] - mn1);
            float p11 = __expf(cs[nb][3] - mn1);
            sum0 += p00 + p01;
            sum1 += p10 + p11;
            uint32_t off0 = SWZ128((uint32_t)(prow0 * 128 + nb * 16 + (lane & 3) * 4));
            uint32_t off1 = SWZ128((uint32_t)((prow0 + 8) * 128 + nb * 16 + (lane & 3) * 4));
            *(uint32_t*)(smem + P_HI + off0) = pack_h2(p00, p01);
            *(uint32_t*)(smem + P_HI + off1) = pack_h2(p10, p11);
        }
        sum0 += __shfl_xor_sync(0xffffffff, sum0, 1);
        sum0 += __shfl_xor_sync(0xffffffff, sum0, 2);
        sum1 += __shfl_xor_sync(0xffffffff, sum1, 1);
        sum1 += __shfl_xor_sync(0xffffffff, sum1, 2);
        l0v = l0v * corr0 + sum0;
        l1v = l1v * corr1 + sum1;

#pragma unroll
        for (int nb = 0; nb < 8; nb++) {
            co[nb][0] *= corr0; co[nb][1] *= corr0;
            co[nb][2] *= corr1; co[nb][3] *= corr1;
        }
        __syncwarp();

        // ---- O += P V (V via ldmatrix.trans) ----
        uint32_t vHiB = sbase + stgo + 8192;
#pragma unroll
        for (int ks = 0; ks < 4; ks++) {
            uint32_t poff = SWZ128((uint32_t)((wid * 16 + lr) * 128 + ks * 32 + lk * 16));
            uint32_t phi[4];
            LDSM_X4(phi[0], phi[1], phi[2], phi[3], sbase + P_HI + poff);
#pragma unroll
            for (int ng = 0; ng < 4; ng++) {
                uint32_t voff = SWZ128((uint32_t)((ks * 16 + lr) * 128 + ng * 32 + lk * 16));
                uint32_t vh0, vh1, vh2, vh3;
                LDSM_X4_T(vh0, vh1, vh2, vh3, vHiB + voff);
                MMAF16(co[ng*2+0], phi, vh0, vh1);
                MMAF16(co[ng*2+1], phi, vh2, vh3);
            }
        }
    }

    // ---- normalize + write fp16 hi ----
    float inv0 = 1.0f / l0v, inv1 = 1.0f / l1v;
    size_t row0 = (size_t)(b * SEQ + gi0) * DIM + h * HD;
    size_t row1 = (size_t)(b * SEQ + gi1) * DIM + h * HD;
#pragma unroll
    for (int nb = 0; nb < 8; nb++) {
        int d = nb * 8 + ccol;
        *(uint32_t*)(out_hi + row0 + d) = pack_h2(co[nb][0] * inv0, co[nb][1] * inv0);
        *(uint32_t*)(out_hi + row1 + d) = pack_h2(co[nb][2] * inv1, co[nb][3] * inv1);
    }
}

// ---------------------------------------------------------------------------
extern "C" void kernel_launch(void* const* d_in, const int* in_sizes, int n_in,
                              void* d_out, int out_size)
{
    const float* x    = (const float*)d_in[0];
    const float* Wqkv = (const float*)d_in[1];
    const float* Wo   = (const float*)d_in[2];
    float* out = (float*)d_out;

    __half *xhi, *wqh, *woh, *qhi, *khi, *vhi, *ahi;
    cudaGetSymbolAddress((void**)&xhi, g_xhi);
    cudaGetSymbolAddress((void**)&wqh, g_wqh);
    cudaGetSymbolAddress((void**)&woh, g_woh);
    cudaGetSymbolAddress((void**)&qhi, g_qhi);
    cudaGetSymbolAddress((void**)&khi, g_khi);
    cudaGetSymbolAddress((void**)&vhi, g_vhi);
    cudaGetSymbolAddress((void**)&ahi, g_ahi);

    cudaFuncSetAttribute(gemm_qkv, cudaFuncAttributeMaxDynamicSharedMemorySize, GEMM_SMEM);
    cudaFuncSetAttribute(gemm_out, cudaFuncAttributeMaxDynamicSharedMemorySize, GEMM_SMEM);
    cudaFuncSetAttribute(attn_mma, cudaFuncAttributeMaxDynamicSharedMemorySize, ATT_SMEM);

    // fused fp16 conversions (x + weights)
    {
        int n4 = N4_X + N4_WQ + N4_WO;
        split_all<<<(n4 + 255) / 256, 256>>>(x, xhi, Wqkv, wqh, Wo, woh);
    }

    // 1) qkv projection -> fp16 Q(hi, scaled), K(hi), V(hi)
    {
        dim3 grid(3 * DIM / BN, NTOK / BM);   // (24, 32)
        gemm_qkv<<<grid, 128, GEMM_SMEM>>>(xhi, wqh, qhi, khi, vhi);
    }

    // 2) tensor-core flash attention (fp16 in, fp16 hi out)
    {
        dim3 grid(SEQ / 128, BATCH * HEADS);   // (16, 32)
        attn_mma<<<grid, 256, ATT_SMEM>>>(qhi, khi, vhi, ahi);
    }

    // 3) out = attn_hi @ Wo^T (fp32 out)
    {
        dim3 grid(DIM / BN, NTOK / BM);        // (8, 32)
        gemm_out<<<grid, 128, GEMM_SMEM>>>(ahi, woh, out);
    }
}

// round 16
// speedup vs baseline: 1.0549x; 1.0549x over previous
#include <cuda_runtime.h>
#include <cuda_fp16.h>
#include <cstdint>

// Problem constants
#define BATCH 2
#define SEQ   2048
#define DIM   1024
#define HEADS 16
#define HD    64
#define NTOK  (BATCH*SEQ)   // 4096
#define LOG2E 1.44269504088896f

// ---------------------------------------------------------------------------
// Scratch (__device__ globals; allocation-free rule)
// ---------------------------------------------------------------------------
__device__ __half g_xhi[(size_t)NTOK * DIM];
__device__ __half g_wqh[(size_t)3 * DIM * DIM];
__device__ __half g_woh[(size_t)DIM * DIM];
__device__ __half g_qhi[(size_t)NTOK * DIM];        // Q (pre-scaled by 0.125*log2e) hi
__device__ __half g_khi[(size_t)NTOK * DIM];        // K hi
__device__ __half g_vhi[(size_t)NTOK * DIM];        // V hi
__device__ __half g_ahi[(size_t)NTOK * DIM];        // attn out hi

// ---------------------------------------------------------------------------
// PTX helpers (baseline sm_100-safe)
// ---------------------------------------------------------------------------
__device__ __forceinline__ uint32_t smem_u32(const void* p) {
    uint32_t a;
    asm("{ .reg .u64 t; cvta.to.shared.u64 t, %1; cvt.u32.u64 %0, t; }" : "=r"(a) : "l"(p));
    return a;
}
#define SWZ128(off) ((off) ^ (((off) >> 3) & 0x70))

#define CP_ASYNC16(saddr, gptr) \
    asm volatile("cp.async.cg.shared.global [%0], [%1], 16;\n" :: "r"(saddr), "l"(gptr))
#define CP_COMMIT() asm volatile("cp.async.commit_group;\n" ::: "memory")
#define CP_WAIT(N)  asm volatile("cp.async.wait_group %0;\n" :: "n"(N) : "memory")

#define LDSM_X4(r0, r1, r2, r3, addr) \
    asm volatile("ldmatrix.sync.aligned.m8n8.x4.shared.b16 {%0,%1,%2,%3}, [%4];" \
                 : "=r"(r0), "=r"(r1), "=r"(r2), "=r"(r3) : "r"(addr))
#define LDSM_X4_T(r0, r1, r2, r3, addr) \
    asm volatile("ldmatrix.sync.aligned.m8n8.x4.trans.shared.b16 {%0,%1,%2,%3}, [%4];" \
                 : "=r"(r0), "=r"(r1), "=r"(r2), "=r"(r3) : "r"(addr))

#define MMAF16(c, a, b0, b1) \
    asm volatile("mma.sync.aligned.m16n8k16.row.col.f32.f16.f16.f32 " \
                 "{%0,%1,%2,%3}, {%4,%5,%6,%7}, {%8,%9}, {%0,%1,%2,%3};" \
                 : "+f"((c)[0]), "+f"((c)[1]), "+f"((c)[2]), "+f"((c)[3]) \
                 : "r"((a)[0]), "r"((a)[1]), "r"((a)[2]), "r"((a)[3]), \
                   "r"(b0), "r"(b1))

// dual-lane approx exp2 on packed fp16
#define EX2_H2(d, a) \
    asm volatile("ex2.approx.f16x2 %0, %1;" : "=r"(d) : "r"(a))

__device__ __forceinline__ uint32_t pack_h2(float a, float b) {
    __half2 v(__float2half(a), __float2half(b));
    return *(uint32_t*)&v;
}

// ---------------------------------------------------------------------------
// fused convert kernel: x, Wqkv, Wo -> fp16
// ---------------------------------------------------------------------------
#define N4_X  (NTOK * DIM / 4)
#define N4_WQ (3 * DIM * DIM / 4)
#define N4_WO (DIM * DIM / 4)

__global__ void split_all(const float* __restrict__ x,  __half* __restrict__ xhi,
                          const float* __restrict__ wq, __half* __restrict__ wqh,
                          const float* __restrict__ wo, __half* __restrict__ woh)
{
    int i = blockIdx.x * blockDim.x + threadIdx.x;
    const float* src; __half* dst;
    if (i < N4_X) { src = x; dst = xhi; }
    else if (i < N4_X + N4_WQ) { i -= N4_X; src = wq; dst = wqh; }
    else if (i < N4_X + N4_WQ + N4_WO) { i -= N4_X + N4_WQ; src = wo; dst = woh; }
    else return;
    float4 v = ((const float4*)src)[i];
    __half2* hp = (__half2*)(dst + (size_t)i * 4);
    hp[0] = __half2(__float2half(v.x), __float2half(v.y));
    hp[1] = __half2(__float2half(v.z), __float2half(v.w));
}

// ---------------------------------------------------------------------------
// 1-term fp16 GEMM: CTA 128x128, 128 threads (4 warps x 64x64), BK=64, 3 stages.
// ---------------------------------------------------------------------------
#define BM 128
#define BN 128
#define BKG 64
#define AG_BYTES (BM * BKG * 2)            // 16384
#define BG_BYTES (BN * BKG * 2)            // 16384
#define STAGE_B (AG_BYTES + BG_BYTES)      // 32768
#define GEMM_SMEM (3 * STAGE_B)            // 98304

#define GEMM_MAINLOOP_1T(Ahi, Bh, K)                                                \
    extern __shared__ __align__(1024) char smem[];                                  \
    const uint32_t sbase = smem_u32(smem);                                          \
    const int tid  = threadIdx.x;                                                   \
    const int wid  = tid >> 5;                                                      \
    const int lane = tid & 31;                                                      \
    const int m0 = blockIdx.y * BM;                                                 \
    const int n0 = blockIdx.x * BN;                                                 \
    const int m_off = (wid & 1) * 64;                                               \
    const int n_off = (wid >> 1) * 64;                                              \
    const __half* aSrc = Ahi + (size_t)m0 * K;                                      \
    const __half* bSrc = Bh + (size_t)n0 * K;                                       \
    const int NIT = K / BKG;                                                        \
    auto load_stage = [&](int sbuf, int k0) {                                       \
        uint32_t stg = sbase + sbuf * STAGE_B;                                      \
        _Pragma("unroll")                                                           \
        for (int r = 0; r < 8; r++) {                                               \
            int idx = r * 128 + tid;                                                \
            int row = idx >> 3, cch = idx & 7;                                      \
            uint32_t soff = SWZ128((uint32_t)(row * 128 + cch * 16));               \
            CP_ASYNC16(stg + soff, aSrc + k0 + (size_t)row * K + cch * 8);          \
        }                                                                           \
        _Pragma("unroll")                                                           \
        for (int r = 0; r < 8; r++) {                                               \
            int idx = r * 128 + tid;                                                \
            int row = idx >> 3, cch = idx & 7;                                      \
            uint32_t soff = SWZ128((uint32_t)(row * 128 + cch * 16));               \
            CP_ASYNC16(stg + AG_BYTES + soff, bSrc + k0 + (size_t)row * K + cch * 8);\
        }                                                                           \
    };                                                                              \
    float c[4][8][4];                                                               \
    _Pragma("unroll")                                                               \
    for (int i = 0; i < 4; i++)                                                     \
        _Pragma("unroll")                                                           \
        for (int j = 0; j < 8; j++)                                                 \
            _Pragma("unroll")                                                       \
            for (int t = 0; t < 4; t++) c[i][j][t] = 0.f;                           \
    load_stage(0, 0); CP_COMMIT();                                                  \
    load_stage(1, BKG); CP_COMMIT();                                                \
    const int lr = lane & 15;                                                       \
    const int lk = lane >> 4;                                                       \
    int sbuf = 0;                                                                   \
    for (int it = 0; it < NIT; it++) {                                              \
        if (it + 1 < NIT) { CP_WAIT(1); } else { CP_WAIT(0); }                      \
        __syncthreads();                                                            \
        if (it + 2 < NIT) { load_stage((sbuf + 2) % 3, (it + 2) * BKG); CP_COMMIT(); } \
        uint32_t stg  = sbase + sbuf * STAGE_B;                                     \
        uint32_t aHiB = stg;                                                        \
        uint32_t bHiB = stg + AG_BYTES;                                             \
        _Pragma("unroll")                                                           \
        for (int ks = 0; ks < 4; ks++) {                                            \
            uint32_t ahi[4][4];                                                     \
            _Pragma("unroll")                                                       \
            for (int mi = 0; mi < 4; mi++) {                                        \
                uint32_t sw = SWZ128((uint32_t)((m_off + mi * 16 + lr) * 128 + ks * 32 + lk * 16)); \
                LDSM_X4(ahi[mi][0], ahi[mi][1], ahi[mi][2], ahi[mi][3], aHiB + sw); \
            }                                                                       \
            _Pragma("unroll")                                                       \
            for (int ng = 0; ng < 4; ng++) {                                        \
                uint32_t sw = SWZ128((uint32_t)((n_off + ng * 16 + lr) * 128 + ks * 32 + lk * 16)); \
                uint32_t bh0, bh1, bh2, bh3;                                        \
                LDSM_X4(bh0, bh1, bh2, bh3, bHiB + sw);                             \
                _Pragma("unroll")                                                   \
                for (int mi = 0; mi < 4; mi++) {                                    \
                    MMAF16(c[mi][ng*2+0], ahi[mi], bh0, bh2);                       \
                    MMAF16(c[mi][ng*2+1], ahi[mi], bh1, bh3);                       \
                }                                                                   \
            }                                                                       \
        }                                                                           \
        sbuf = (sbuf + 1) % 3;                                                      \
    }                                                                               \
    const int cr = lane >> 2;                                                       \
    const int cc = (lane & 3) * 2;

// ---------------------------------------------------------------------------
// GEMM1: qkv projection, epilogue -> Q(hi, scaled by 0.125*log2e), K(hi), V(hi)
// ---------------------------------------------------------------------------
__global__ __launch_bounds__(128, 2)
void gemm_qkv(const __half* __restrict__ Ahi, const __half* __restrict__ Bh,
              __half* __restrict__ qhi, __half* __restrict__ khi,
              __half* __restrict__ vhi)
{
    GEMM_MAINLOOP_1T(Ahi, Bh, DIM)

    const int seg  = n0 >> 10;           // 0=Q, 1=K, 2=V
    const int col0 = (n0 & 1023) + n_off;
    __half* dst = (seg == 0) ? qhi : (seg == 1) ? khi : vhi;
    const float sc = (seg == 0) ? (0.125f * LOG2E) : 1.0f;
#pragma unroll
    for (int mi = 0; mi < 4; mi++) {
        int r0 = m0 + m_off + mi * 16 + cr;
#pragma unroll
        for (int j = 0; j < 8; j++) {
            int col = col0 + j * 8 + cc;
            *(uint32_t*)(dst + (size_t)r0 * DIM + col) =
                pack_h2(c[mi][j][0] * sc, c[mi][j][1] * sc);
            *(uint32_t*)(dst + (size_t)(r0 + 8) * DIM + col) =
                pack_h2(c[mi][j][2] * sc, c[mi][j][3] * sc);
        }
    }
}

// ---------------------------------------------------------------------------
// GEMM2: out projection, fp32 out
// ---------------------------------------------------------------------------
__global__ __launch_bounds__(128, 2)
void gemm_out(const __half* __restrict__ Ahi, const __half* __restrict__ Bh,
              float* __restrict__ C)
{
    GEMM_MAINLOOP_1T(Ahi, Bh, DIM)

#pragma unroll
    for (int mi = 0; mi < 4; mi++) {
        int r0 = m0 + m_off + mi * 16 + cr;
#pragma unroll
        for (int j = 0; j < 8; j++) {
            int col = n0 + n_off + j * 8 + cc;
            *(float2*)(C + (size_t)r0 * DIM + col)       = make_float2(c[mi][j][0], c[mi][j][1]);
            *(float2*)(C + (size_t)(r0 + 8) * DIM + col) = make_float2(c[mi][j][2], c[mi][j][3]);
        }
    }
}

// ---------------------------------------------------------------------------
// Flash attention (base-2 domain): S2 = Q·K (pre-scaled) - slope2*rel;
// P = ex2(S2 - max) via ex2.approx.f16x2; l via ones-column MMA.
// 3-stage K/V cp.async pipeline, one __syncthreads per key-tile.
// ---------------------------------------------------------------------------
#define ATT_SMEM 81920
#define Q_HI 0
#define STG0 16384
#define P_HI 65536

__global__ __launch_bounds__(256, 2)
void attn_mma(const __half* __restrict__ qhi,
              const __half* __restrict__ khi, const __half* __restrict__ vhi,
              __half* __restrict__ out_hi)
{
    extern __shared__ __align__(1024) char smem[];
    const uint32_t sbase = smem_u32(smem);
    const int tid  = threadIdx.x;
    const int wid  = tid >> 5;
    const int lane = tid & 31;
    const int lr   = lane & 15;
    const int lk   = lane >> 4;

    const int qt = (int)(gridDim.x - 1 - blockIdx.x);   // largest tiles first
    const int bh = blockIdx.y;
    const int b  = bh >> 4;
    const int h  = bh & 15;
    const int q0 = qt * 128;

    const float slope2 = exp2f(-0.5f * (float)(h + 1)) * LOG2E;

    const __half* qh_base = qhi + (size_t)(b * SEQ) * DIM + h * HD;
    const __half* kh_base = khi + (size_t)(b * SEQ) * DIM + h * HD;
    const __half* vh_base = vhi + (size_t)(b * SEQ) * DIM + h * HD;

    // ---- issue Q tile loads ----
#pragma unroll
    for (int r = 0; r < 4; r++) {
        int idx = r * 256 + tid;
        int row = idx >> 3;
        int ch  = idx & 7;
        uint32_t soff = SWZ128((uint32_t)(row * 128 + ch * 16));
        CP_ASYNC16(sbase + Q_HI + soff, qh_base + (size_t)(q0 + row) * DIM + ch * 8);
    }

    const int nkt = 2 * qt + 2;

    auto issue_kv = [&](int kt, int s) {
        uint32_t stg = sbase + STG0 + s * 16384;
        int k0 = kt * 64;
#pragma unroll
        for (int r = 0; r < 2; r++) {
            int idx = r * 256 + tid;
            int row = idx >> 3;
            int ch  = idx & 7;
            uint32_t soff = SWZ128((uint32_t)(row * 128 + ch * 16));
            CP_ASYNC16(stg + soff,        kh_base + (size_t)(k0 + row) * DIM + ch * 8);
            CP_ASYNC16(stg + 8192 + soff, vh_base + (size_t)(k0 + row) * DIM + ch * 8);
        }
    };

    issue_kv(0, 0);
    CP_COMMIT();
    issue_kv(1, 1);
    CP_COMMIT();

    float cs[8][4];
    float co[8][4];
#pragma unroll
    for (int j = 0; j < 8; j++)
#pragma unroll
        for (int t = 0; t < 4; t++) co[j][t] = 0.f;

    float m0v = -1e30f, m1v = -1e30f, l0v = 0.f, l1v = 0.f;

    const int r0 = lane >> 2;
    const int ccol = (lane & 3) * 2;
    const int gi0 = q0 + wid * 16 + r0;
    const int gi1 = gi0 + 8;
    const uint32_t ONES2 = 0x3C003C00u;   // half2(1.0, 1.0)

    for (int kt = 0; kt < nkt; kt++) {
        const int s = kt % 3;
        const int k0 = kt * 64;
        const uint32_t stgo = STG0 + s * 16384;

        if (kt + 1 < nkt) { CP_WAIT(1); } else { CP_WAIT(0); }
        __syncthreads();
        if (kt + 2 < nkt) { issue_kv(kt + 2, (kt + 2) % 3); CP_COMMIT(); }

        // Fully-masked warps skip the diagonal tile's compute.
        if (kt == nkt - 1 && wid < 4) continue;

        // ---- S2 = Q K^T (already in log2 domain) ----
#pragma unroll
        for (int j = 0; j < 8; j++)
#pragma unroll
            for (int t = 0; t < 4; t++) cs[j][t] = 0.f;

        uint32_t kHiB = sbase + stgo;
#pragma unroll
        for (int ks = 0; ks < 4; ks++) {
            uint32_t qoff = SWZ128((uint32_t)((wid * 16 + lr) * 128 + ks * 32 + lk * 16));
            uint32_t ahi[4];
            LDSM_X4(ahi[0], ahi[1], ahi[2], ahi[3], sbase + Q_HI + qoff);
#pragma unroll
            for (int ng = 0; ng < 4; ng++) {
                uint32_t boff = SWZ128((uint32_t)((ng * 16 + lr) * 128 + ks * 32 + lk * 16));
                uint32_t bh0, bh1, bh2, bh3;
                LDSM_X4(bh0, bh1, bh2, bh3, kHiB + boff);
                MMAF16(cs[ng*2+0], ahi, bh0, bh2);
                MMAF16(cs[ng*2+1], ahi, bh1, bh3);
            }
        }

        // ---- ALiBi + causal mask (log2 domain) ----
#pragma unroll
        for (int nb = 0; nb < 8; nb++) {
#pragma unroll
            for (int cidx = 0; cidx < 2; cidx++) {
                int gj = k0 + nb * 8 + ccol + cidx;
                float rel0 = slope2 * (float)(gj - gi0);
                float rel1 = slope2 * (float)(gj - gi1);
                cs[nb][cidx]     = (gj > gi0) ? -1e30f : cs[nb][cidx]     - rel0;
                cs[nb][2 + cidx] = (gj > gi1) ? -1e30f : cs[nb][2 + cidx] - rel1;
            }
        }

        // ---- online softmax (max + corr) ----
        float mx0 = -1e30f, mx1 = -1e30f;
#pragma unroll
        for (int nb = 0; nb < 8; nb++) {
            mx0 = fmaxf(mx0, fmaxf(cs[nb][0], cs[nb][1]));
            mx1 = fmaxf(mx1, fmaxf(cs[nb][2], cs[nb][3]));
        }
        mx0 = fmaxf(mx0, __shfl_xor_sync(0xffffffff, mx0, 1));
        mx0 = fmaxf(mx0, __shfl_xor_sync(0xffffffff, mx0, 2));
        mx1 = fmaxf(mx1, __shfl_xor_sync(0xffffffff, mx1, 1));
        mx1 = fmaxf(mx1, __shfl_xor_sync(0xffffffff, mx1, 2));

        float mn0 = fmaxf(m0v, mx0), mn1 = fmaxf(m1v, mx1);
        float corr0 = exp2f(m0v - mn0), corr1 = exp2f(m1v - mn1);
        m0v = mn0; m1v = mn1;

        // ---- P = ex2(S2 - max) in fp16x2; store to smem ----
        const int prow0 = wid * 16 + r0;
#pragma unroll
        for (int nb = 0; nb < 8; nb++) {
            uint32_t ph0 = pack_h2(cs[nb][0] - mn0, cs[nb][1] - mn0);
            uint32_t ph1 = pack_h2(cs[nb][2] - mn1, cs[nb][3] - mn1);
            EX2_H2(ph0, ph0);
            EX2_H2(ph1, ph1);
            uint32_t off0 = SWZ128((uint32_t)(prow0 * 128 + nb * 16 + (lane & 3) * 4));
            uint32_t off1 = SWZ128((uint32_t)((prow0 + 8) * 128 + nb * 16 + (lane & 3) * 4));
            *(uint32_t*)(smem + P_HI + off0) = ph0;
            *(uint32_t*)(smem + P_HI + off1) = ph1;
        }

#pragma unroll
        for (int nb = 0; nb < 8; nb++) {
            co[nb][0] *= corr0; co[nb][1] *= corr0;
            co[nb][2] *= corr1; co[nb][3] *= corr1;
        }
        __syncwarp();

        // ---- O += P V; l via ones-column MMA ----
        float cl[4] = {0.f, 0.f, 0.f, 0.f};
        uint32_t vHiB = sbase + stgo + 8192;
#pragma unroll
        for (int ks = 0; ks < 4; ks++) {
            uint32_t poff = SWZ128((uint32_t)((wid * 16 + lr) * 128 + ks * 32 + lk * 16));
            uint32_t phi[4];
            LDSM_X4(phi[0], phi[1], phi[2], phi[3], sbase + P_HI + poff);
            MMAF16(cl, phi, ONES2, ONES2);
#pragma unroll
            for (int ng = 0; ng < 4; ng++) {
                uint32_t voff = SWZ128((uint32_t)((ks * 16 + lr) * 128 + ng * 32 + lk * 16));
                uint32_t vh0, vh1, vh2, vh3;
                LDSM_X4_T(vh0, vh1, vh2, vh3, vHiB + voff);
                MMAF16(co[ng*2+0], phi, vh0, vh1);
                MMAF16(co[ng*2+1], phi, vh2, vh3);
            }
        }
        l0v = l0v * corr0 + cl[0];
        l1v = l1v * corr1 + cl[2];
    }

    // ---- normalize + write fp16 hi ----
    float inv0 = 1.0f / l0v, inv1 = 1.0f / l1v;
    size_t row0 = (size_t)(b * SEQ + gi0) * DIM + h * HD;
    size_t row1 = (size_t)(b * SEQ + gi1) * DIM + h * HD;
#pragma unroll
    for (int nb = 0; nb < 8; nb++) {
        int d = nb * 8 + ccol;
        *(uint32_t*)(out_hi + row0 + d) = pack_h2(co[nb][0] * inv0, co[nb][1] * inv0);
        *(uint32_t*)(out_hi + row1 + d) = pack_h2(co[nb][2] * inv1, co[nb][3] * inv1);
    }
}

// ---------------------------------------------------------------------------
extern "C" void kernel_launch(void* const* d_in, const int* in_sizes, int n_in,
                              void* d_out, int out_size)
{
    const float* x    = (const float*)d_in[0];
    const float* Wqkv = (const float*)d_in[1];
    const float* Wo   = (const float*)d_in[2];
    float* out = (float*)d_out;

    __half *xhi, *wqh, *woh, *qhi, *khi, *vhi, *ahi;
    cudaGetSymbolAddress((void**)&xhi, g_xhi);
    cudaGetSymbolAddress((void**)&wqh, g_wqh);
    cudaGetSymbolAddress((void**)&woh, g_woh);
    cudaGetSymbolAddress((void**)&qhi, g_qhi);
    cudaGetSymbolAddress((void**)&khi, g_khi);
    cudaGetSymbolAddress((void**)&vhi, g_vhi);
    cudaGetSymbolAddress((void**)&ahi, g_ahi);

    cudaFuncSetAttribute(gemm_qkv, cudaFuncAttributeMaxDynamicSharedMemorySize, GEMM_SMEM);
    cudaFuncSetAttribute(gemm_out, cudaFuncAttributeMaxDynamicSharedMemorySize, GEMM_SMEM);
    cudaFuncSetAttribute(attn_mma, cudaFuncAttributeMaxDynamicSharedMemorySize, ATT_SMEM);

    // fused fp16 conversions (x + weights)
    {
        int n4 = N4_X + N4_WQ + N4_WO;
        split_all<<<(n4 + 255) / 256, 256>>>(x, xhi, Wqkv, wqh, Wo, woh);
    }

    // 1) qkv projection -> fp16 Q(hi, scaled), K(hi), V(hi)
    {
        dim3 grid(3 * DIM / BN, NTOK / BM);   // (24, 32)
        gemm_qkv<<<grid, 128, GEMM_SMEM>>>(xhi, wqh, qhi, khi, vhi);
    }

    // 2) tensor-core flash attention (fp16 in, fp16 hi out)
    {
        dim3 grid(SEQ / 128, BATCH * HEADS);   // (16, 32)
        attn_mma<<<grid, 256, ATT_SMEM>>>(qhi, khi, vhi, ahi);
    }

    // 3) out = attn_hi @ Wo^T (fp32 out)
    {
        dim3 grid(DIM / BN, NTOK / BM);        // (8, 32)
        gemm_out<<<grid, 128, GEMM_SMEM>>>(ahi, woh, out);
    }
}

// round 17
// speedup vs baseline: 1.0581x; 1.0030x over previous
#include <cuda_runtime.h>
#include <cuda_fp16.h>
#include <cstdint>

// Problem constants
#define BATCH 2
#define SEQ   2048
#define DIM   1024
#define HEADS 16
#define HD    64
#define NTOK  (BATCH*SEQ)   // 4096
#define LOG2E 1.44269504088896f

// ---------------------------------------------------------------------------
// Scratch (__device__ globals; allocation-free rule)
// ---------------------------------------------------------------------------
__device__ __half g_xhi[(size_t)NTOK * DIM];
__device__ __half g_wqh[(size_t)3 * DIM * DIM];
__device__ __half g_woh[(size_t)DIM * DIM];
__device__ __half g_qhi[(size_t)NTOK * DIM];        // Q (pre-scaled by 0.125*log2e) hi
__device__ __half g_khi[(size_t)NTOK * DIM];        // K hi
__device__ __half g_vhi[(size_t)NTOK * DIM];        // V hi
__device__ __half g_ahi[(size_t)NTOK * DIM];        // attn out hi

// ---------------------------------------------------------------------------
// PTX helpers (baseline sm_100-safe)
// ---------------------------------------------------------------------------
__device__ __forceinline__ uint32_t smem_u32(const void* p) {
    uint32_t a;
    asm("{ .reg .u64 t; cvta.to.shared.u64 t, %1; cvt.u32.u64 %0, t; }" : "=r"(a) : "l"(p));
    return a;
}
#define SWZ128(off) ((off) ^ (((off) >> 3) & 0x70))

#define CP_ASYNC16(saddr, gptr) \
    asm volatile("cp.async.cg.shared.global [%0], [%1], 16;\n" :: "r"(saddr), "l"(gptr))
#define CP_COMMIT() asm volatile("cp.async.commit_group;\n" ::: "memory")
#define CP_WAIT(N)  asm volatile("cp.async.wait_group %0;\n" :: "n"(N) : "memory")

#define LDSM_X4(r0, r1, r2, r3, addr) \
    asm volatile("ldmatrix.sync.aligned.m8n8.x4.shared.b16 {%0,%1,%2,%3}, [%4];" \
                 : "=r"(r0), "=r"(r1), "=r"(r2), "=r"(r3) : "r"(addr))
#define LDSM_X4_T(r0, r1, r2, r3, addr) \
    asm volatile("ldmatrix.sync.aligned.m8n8.x4.trans.shared.b16 {%0,%1,%2,%3}, [%4];" \
                 : "=r"(r0), "=r"(r1), "=r"(r2), "=r"(r3) : "r"(addr))

#define MMAF16(c, a, b0, b1) \
    asm volatile("mma.sync.aligned.m16n8k16.row.col.f32.f16.f16.f32 " \
                 "{%0,%1,%2,%3}, {%4,%5,%6,%7}, {%8,%9}, {%0,%1,%2,%3};" \
                 : "+f"((c)[0]), "+f"((c)[1]), "+f"((c)[2]), "+f"((c)[3]) \
                 : "r"((a)[0]), "r"((a)[1]), "r"((a)[2]), "r"((a)[3]), \
                   "r"(b0), "r"(b1))

// dual-lane approx exp2 on packed fp16
#define EX2_H2(d, a) \
    asm volatile("ex2.approx.f16x2 %0, %1;" : "=r"(d) : "r"(a))

__device__ __forceinline__ uint32_t pack_h2(float a, float b) {
    __half2 v(__float2half(a), __float2half(b));
    return *(uint32_t*)&v;
}

// ---------------------------------------------------------------------------
// fused convert kernel: x, Wqkv, Wo -> fp16
// ---------------------------------------------------------------------------
#define N4_X  (NTOK * DIM / 4)
#define N4_WQ (3 * DIM * DIM / 4)
#define N4_WO (DIM * DIM / 4)

__global__ void split_all(const float* __restrict__ x,  __half* __restrict__ xhi,
                          const float* __restrict__ wq, __half* __restrict__ wqh,
                          const float* __restrict__ wo, __half* __restrict__ woh)
{
    int i = blockIdx.x * blockDim.x + threadIdx.x;
    const float* src; __half* dst;
    if (i < N4_X) { src = x; dst = xhi; }
    else if (i < N4_X + N4_WQ) { i -= N4_X; src = wq; dst = wqh; }
    else if (i < N4_X + N4_WQ + N4_WO) { i -= N4_X + N4_WQ; src = wo; dst = woh; }
    else return;
    float4 v = ((const float4*)src)[i];
    __half2* hp = (__half2*)(dst + (size_t)i * 4);
    hp[0] = __half2(__float2half(v.x), __float2half(v.y));
    hp[1] = __half2(__float2half(v.z), __float2half(v.w));
}

// ---------------------------------------------------------------------------
// 1-term fp16 GEMM: CTA 128x128, 128 threads (4 warps x 64x64), BK=64, 3 stages.
// ---------------------------------------------------------------------------
#define BM 128
#define BN 128
#define BKG 64
#define AG_BYTES (BM * BKG * 2)            // 16384
#define BG_BYTES (BN * BKG * 2)            // 16384
#define STAGE_B (AG_BYTES + BG_BYTES)      // 32768
#define GEMM_SMEM (3 * STAGE_B)            // 98304

#define GEMM_MAINLOOP_1T(Ahi, Bh, K)                                                \
    extern __shared__ __align__(1024) char smem[];                                  \
    const uint32_t sbase = smem_u32(smem);                                          \
    const int tid  = threadIdx.x;                                                   \
    const int wid  = tid >> 5;                                                      \
    const int lane = tid & 31;                                                      \
    const int m0 = blockIdx.y * BM;                                                 \
    const int n0 = blockIdx.x * BN;                                                 \
    const int m_off = (wid & 1) * 64;                                               \
    const int n_off = (wid >> 1) * 64;                                              \
    const __half* aSrc = Ahi + (size_t)m0 * K;                                      \
    const __half* bSrc = Bh + (size_t)n0 * K;                                       \
    const int NIT = K / BKG;                                                        \
    auto load_stage = [&](int sbuf, int k0) {                                       \
        uint32_t stg = sbase + sbuf * STAGE_B;                                      \
        _Pragma("unroll")                                                           \
        for (int r = 0; r < 8; r++) {                                               \
            int idx = r * 128 + tid;                                                \
            int row = idx >> 3, cch = idx & 7;                                      \
            uint32_t soff = SWZ128((uint32_t)(row * 128 + cch * 16));               \
            CP_ASYNC16(stg + soff, aSrc + k0 + (size_t)row * K + cch * 8);          \
        }                                                                           \
        _Pragma("unroll")                                                           \
        for (int r = 0; r < 8; r++) {                                               \
            int idx = r * 128 + tid;                                                \
            int row = idx >> 3, cch = idx & 7;                                      \
            uint32_t soff = SWZ128((uint32_t)(row * 128 + cch * 16));               \
            CP_ASYNC16(stg + AG_BYTES + soff, bSrc + k0 + (size_t)row * K + cch * 8);\
        }                                                                           \
    };                                                                              \
    float c[4][8][4];                                                               \
    _Pragma("unroll")                                                               \
    for (int i = 0; i < 4; i++)                                                     \
        _Pragma("unroll")                                                           \
        for (int j = 0; j < 8; j++)                                                 \
            _Pragma("unroll")                                                       \
            for (int t = 0; t < 4; t++) c[i][j][t] = 0.f;                           \
    load_stage(0, 0); CP_COMMIT();                                                  \
    load_stage(1, BKG); CP_COMMIT();                                                \
    const int lr = lane & 15;                                                       \
    const int lk = lane >> 4;                                                       \
    int sbuf = 0;                                                                   \
    for (int it = 0; it < NIT; it++) {                                              \
        if (it + 1 < NIT) { CP_WAIT(1); } else { CP_WAIT(0); }                      \
        __syncthreads();                                                            \
        if (it + 2 < NIT) { load_stage((sbuf + 2) % 3, (it + 2) * BKG); CP_COMMIT(); } \
        uint32_t stg  = sbase + sbuf * STAGE_B;                                     \
        uint32_t aHiB = stg;                                                        \
        uint32_t bHiB = stg + AG_BYTES;                                             \
        _Pragma("unroll")                                                           \
        for (int ks = 0; ks < 4; ks++) {                                            \
            uint32_t ahi[4][4];                                                     \
            _Pragma("unroll")                                                       \
            for (int mi = 0; mi < 4; mi++) {                                        \
                uint32_t sw = SWZ128((uint32_t)((m_off + mi * 16 + lr) * 128 + ks * 32 + lk * 16)); \
                LDSM_X4(ahi[mi][0], ahi[mi][1], ahi[mi][2], ahi[mi][3], aHiB + sw); \
            }                                                                       \
            _Pragma("unroll")                                                       \
            for (int ng = 0; ng < 4; ng++) {                                        \
                uint32_t sw = SWZ128((uint32_t)((n_off + ng * 16 + lr) * 128 + ks * 32 + lk * 16)); \
                uint32_t bh0, bh1, bh2, bh3;                                        \
                LDSM_X4(bh0, bh1, bh2, bh3, bHiB + sw);                             \
                _Pragma("unroll")                                                   \
                for (int mi = 0; mi < 4; mi++) {                                    \
                    MMAF16(c[mi][ng*2+0], ahi[mi], bh0, bh2);                       \
                    MMAF16(c[mi][ng*2+1], ahi[mi], bh1, bh3);                       \
                }                                                                   \
            }                                                                       \
        }                                                                           \
        sbuf = (sbuf + 1) % 3;                                                      \
    }                                                                               \
    const int cr = lane >> 2;                                                       \
    const int cc = (lane & 3) * 2;

// ---------------------------------------------------------------------------
// GEMM1: qkv projection, epilogue -> Q(hi, scaled by 0.125*log2e), K(hi), V(hi)
// ---------------------------------------------------------------------------
__global__ __launch_bounds__(128, 2)
void gemm_qkv(const __half* __restrict__ Ahi, const __half* __restrict__ Bh,
              __half* __restrict__ qhi, __half* __restrict__ khi,
              __half* __restrict__ vhi)
{
    GEMM_MAINLOOP_1T(Ahi, Bh, DIM)

    const int seg  = n0 >> 10;           // 0=Q, 1=K, 2=V
    const int col0 = (n0 & 1023) + n_off;
    __half* dst = (seg == 0) ? qhi : (seg == 1) ? khi : vhi;
    const float sc = (seg == 0) ? (0.125f * LOG2E) : 1.0f;
#pragma unroll
    for (int mi = 0; mi < 4; mi++) {
        int r0 = m0 + m_off + mi * 16 + cr;
#pragma unroll
        for (int j = 0; j < 8; j++) {
            int col = col0 + j * 8 + cc;
            *(uint32_t*)(dst + (size_t)r0 * DIM + col) =
                pack_h2(c[mi][j][0] * sc, c[mi][j][1] * sc);
            *(uint32_t*)(dst + (size_t)(r0 + 8) * DIM + col) =
                pack_h2(c[mi][j][2] * sc, c[mi][j][3] * sc);
        }
    }
}

// ---------------------------------------------------------------------------
// GEMM2: out projection, fp32 out
// ---------------------------------------------------------------------------
__global__ __launch_bounds__(128, 2)
void gemm_out(const __half* __restrict__ Ahi, const __half* __restrict__ Bh,
              float* __restrict__ C)
{
    GEMM_MAINLOOP_1T(Ahi, Bh, DIM)

#pragma unroll
    for (int mi = 0; mi < 4; mi++) {
        int r0 = m0 + m_off + mi * 16 + cr;
#pragma unroll
        for (int j = 0; j < 8; j++) {
            int col = n0 + n_off + j * 8 + cc;
            *(float2*)(C + (size_t)r0 * DIM + col)       = make_float2(c[mi][j][0], c[mi][j][1]);
            *(float2*)(C + (size_t)(r0 + 8) * DIM + col) = make_float2(c[mi][j][2], c[mi][j][3]);
        }
    }
}

// ---------------------------------------------------------------------------
// Flash attention (base-2 domain, register-resident P):
// S2 = Q·K - slope2*rel; P = ex2.f16x2(S2-max) kept in registers and fed
// DIRECTLY as the A-fragment of the PV MMA (C-frag layout == A-frag layout).
// l via ones-column MMA on the same fragments. No P smem, no syncwarp.
// smem: Q 16384 + 3 KV stages 16384 -> 65536; 2 CTAs/SM.
// ---------------------------------------------------------------------------
#define ATT_SMEM 65536
#define Q_HI 0
#define STG0 16384

__global__ __launch_bounds__(256, 2)
void attn_mma(const __half* __restrict__ qhi,
              const __half* __restrict__ khi, const __half* __restrict__ vhi,
              __half* __restrict__ out_hi)
{
    extern __shared__ __align__(1024) char smem[];
    const uint32_t sbase = smem_u32(smem);
    const int tid  = threadIdx.x;
    const int wid  = tid >> 5;
    const int lane = tid & 31;
    const int lr   = lane & 15;
    const int lk   = lane >> 4;

    const int qt = (int)(gridDim.x - 1 - blockIdx.x);   // largest tiles first
    const int bh = blockIdx.y;
    const int b  = bh >> 4;
    const int h  = bh & 15;
    const int q0 = qt * 128;

    const float slope2 = exp2f(-0.5f * (float)(h + 1)) * LOG2E;

    const __half* qh_base = qhi + (size_t)(b * SEQ) * DIM + h * HD;
    const __half* kh_base = khi + (size_t)(b * SEQ) * DIM + h * HD;
    const __half* vh_base = vhi + (size_t)(b * SEQ) * DIM + h * HD;

    // ---- issue Q tile loads ----
#pragma unroll
    for (int r = 0; r < 4; r++) {
        int idx = r * 256 + tid;
        int row = idx >> 3;
        int ch  = idx & 7;
        uint32_t soff = SWZ128((uint32_t)(row * 128 + ch * 16));
        CP_ASYNC16(sbase + Q_HI + soff, qh_base + (size_t)(q0 + row) * DIM + ch * 8);
    }

    const int nkt = 2 * qt + 2;

    auto issue_kv = [&](int kt, int s) {
        uint32_t stg = sbase + STG0 + s * 16384;
        int k0 = kt * 64;
#pragma unroll
        for (int r = 0; r < 2; r++) {
            int idx = r * 256 + tid;
            int row = idx >> 3;
            int ch  = idx & 7;
            uint32_t soff = SWZ128((uint32_t)(row * 128 + ch * 16));
            CP_ASYNC16(stg + soff,        kh_base + (size_t)(k0 + row) * DIM + ch * 8);
            CP_ASYNC16(stg + 8192 + soff, vh_base + (size_t)(k0 + row) * DIM + ch * 8);
        }
    };

    issue_kv(0, 0);
    CP_COMMIT();
    issue_kv(1, 1);
    CP_COMMIT();

    float cs[8][4];
    float co[8][4];
#pragma unroll
    for (int j = 0; j < 8; j++)
#pragma unroll
        for (int t = 0; t < 4; t++) co[j][t] = 0.f;

    float m0v = -1e30f, m1v = -1e30f, l0v = 0.f, l1v = 0.f;

    const int r0 = lane >> 2;
    const int ccol = (lane & 3) * 2;
    const int gi0 = q0 + wid * 16 + r0;
    const int gi1 = gi0 + 8;
    const uint32_t ONES2 = 0x3C003C00u;   // half2(1.0, 1.0)

    for (int kt = 0; kt < nkt; kt++) {
        const int s = kt % 3;
        const int k0 = kt * 64;
        const uint32_t stgo = STG0 + s * 16384;

        if (kt + 1 < nkt) { CP_WAIT(1); } else { CP_WAIT(0); }
        __syncthreads();
        if (kt + 2 < nkt) { issue_kv(kt + 2, (kt + 2) % 3); CP_COMMIT(); }

        // Fully-masked warps skip the diagonal tile's compute.
        if (kt == nkt - 1 && wid < 4) continue;

        // ---- S2 = Q K^T (log2 domain) ----
#pragma unroll
        for (int j = 0; j < 8; j++)
#pragma unroll
            for (int t = 0; t < 4; t++) cs[j][t] = 0.f;

        uint32_t kHiB = sbase + stgo;
#pragma unroll
        for (int ks = 0; ks < 4; ks++) {
            uint32_t qoff = SWZ128((uint32_t)((wid * 16 + lr) * 128 + ks * 32 + lk * 16));
            uint32_t ahi[4];
            LDSM_X4(ahi[0], ahi[1], ahi[2], ahi[3], sbase + Q_HI + qoff);
#pragma unroll
            for (int ng = 0; ng < 4; ng++) {
                uint32_t boff = SWZ128((uint32_t)((ng * 16 + lr) * 128 + ks * 32 + lk * 16));
                uint32_t bh0, bh1, bh2, bh3;
                LDSM_X4(bh0, bh1, bh2, bh3, kHiB + boff);
                MMAF16(cs[ng*2+0], ahi, bh0, bh2);
                MMAF16(cs[ng*2+1], ahi, bh1, bh3);
            }
        }

        // ---- ALiBi + causal mask (log2 domain) ----
#pragma unroll
        for (int nb = 0; nb < 8; nb++) {
#pragma unroll
            for (int cidx = 0; cidx < 2; cidx++) {
                int gj = k0 + nb * 8 + ccol + cidx;
                float rel0 = slope2 * (float)(gj - gi0);
                float rel1 = slope2 * (float)(gj - gi1);
                cs[nb][cidx]     = (gj > gi0) ? -1e30f : cs[nb][cidx]     - rel0;
                cs[nb][2 + cidx] = (gj > gi1) ? -1e30f : cs[nb][2 + cidx] - rel1;
            }
        }

        // ---- online softmax (max + corr) ----
        float mx0 = -1e30f, mx1 = -1e30f;
#pragma unroll
        for (int nb = 0; nb < 8; nb++) {
            mx0 = fmaxf(mx0, fmaxf(cs[nb][0], cs[nb][1]));
            mx1 = fmaxf(mx1, fmaxf(cs[nb][2], cs[nb][3]));
        }
        mx0 = fmaxf(mx0, __shfl_xor_sync(0xffffffff, mx0, 1));
        mx0 = fmaxf(mx0, __shfl_xor_sync(0xffffffff, mx0, 2));
        mx1 = fmaxf(mx1, __shfl_xor_sync(0xffffffff, mx1, 1));
        mx1 = fmaxf(mx1, __shfl_xor_sync(0xffffffff, mx1, 2));

        float mn0 = fmaxf(m0v, mx0), mn1 = fmaxf(m1v, mx1);
        float corr0 = exp2f(m0v - mn0), corr1 = exp2f(m1v - mn1);
        m0v = mn0; m1v = mn1;

        // ---- P = ex2(S2 - max) in fp16x2 REGISTERS (A-fragment layout) ----
        uint32_t pex0[8], pex1[8];
#pragma unroll
        for (int nb = 0; nb < 8; nb++) {
            uint32_t ph0 = pack_h2(cs[nb][0] - mn0, cs[nb][1] - mn0);
            uint32_t ph1 = pack_h2(cs[nb][2] - mn1, cs[nb][3] - mn1);
            EX2_H2(pex0[nb], ph0);
            EX2_H2(pex1[nb], ph1);
        }

#pragma unroll
        for (int nb = 0; nb < 8; nb++) {
            co[nb][0] *= corr0; co[nb][1] *= corr0;
            co[nb][2] *= corr1; co[nb][3] *= corr1;
        }

        // ---- O += P V; l via ones-column MMA (P straight from registers) ----
        float cl[4] = {0.f, 0.f, 0.f, 0.f};
        uint32_t vHiB = sbase + stgo + 8192;
#pragma unroll
        for (int ks = 0; ks < 4; ks++) {
            uint32_t af[4] = { pex0[2*ks], pex1[2*ks], pex0[2*ks+1], pex1[2*ks+1] };
            MMAF16(cl, af, ONES2, ONES2);
#pragma unroll
            for (int ng = 0; ng < 4; ng++) {
                uint32_t voff = SWZ128((uint32_t)((ks * 16 + lr) * 128 + ng * 32 + lk * 16));
                uint32_t vh0, vh1, vh2, vh3;
                LDSM_X4_T(vh0, vh1, vh2, vh3, vHiB + voff);
                MMAF16(co[ng*2+0], af, vh0, vh1);
                MMAF16(co[ng*2+1], af, vh2, vh3);
            }
        }
        l0v = l0v * corr0 + cl[0];
        l1v = l1v * corr1 + cl[2];
    }

    // ---- normalize + write fp16 hi ----
    float inv0 = 1.0f / l0v, inv1 = 1.0f / l1v;
    size_t row0 = (size_t)(b * SEQ + gi0) * DIM + h * HD;
    size_t row1 = (size_t)(b * SEQ + gi1) * DIM + h * HD;
#pragma unroll
    for (int nb = 0; nb < 8; nb++) {
        int d = nb * 8 + ccol;
        *(uint32_t*)(out_hi + row0 + d) = pack_h2(co[nb][0] * inv0, co[nb][1] * inv0);
        *(uint32_t*)(out_hi + row1 + d) = pack_h2(co[nb][2] * inv1, co[nb][3] * inv1);
    }
}

// ---------------------------------------------------------------------------
extern "C" void kernel_launch(void* const* d_in, const int* in_sizes, int n_in,
                              void* d_out, int out_size)
{
    const float* x    = (const float*)d_in[0];
    const float* Wqkv = (const float*)d_in[1];
    const float* Wo   = (const float*)d_in[2];
    float* out = (float*)d_out;

    __half *xhi, *wqh, *woh, *qhi, *khi, *vhi, *ahi;
    cudaGetSymbolAddress((void**)&xhi, g_xhi);
    cudaGetSymbolAddress((void**)&wqh, g_wqh);
    cudaGetSymbolAddress((void**)&woh, g_woh);
    cudaGetSymbolAddress((void**)&qhi, g_qhi);
    cudaGetSymbolAddress((void**)&khi, g_khi);
    cudaGetSymbolAddress((void**)&vhi, g_vhi);
    cudaGetSymbolAddress((void**)&ahi, g_ahi);

    cudaFuncSetAttribute(gemm_qkv, cudaFuncAttributeMaxDynamicSharedMemorySize, GEMM_SMEM);
    cudaFuncSetAttribute(gemm_out, cudaFuncAttributeMaxDynamicSharedMemorySize, GEMM_SMEM);
    cudaFuncSetAttribute(attn_mma, cudaFuncAttributeMaxDynamicSharedMemorySize, ATT_SMEM);

    // fused fp16 conversions (x + weights)
    {
        int n4 = N4_X + N4_WQ + N4_WO;
        split_all<<<(n4 + 255) / 256, 256>>>(x, xhi, Wqkv, wqh, Wo, woh);
    }

    // 1) qkv projection -> fp16 Q(hi, scaled), K(hi), V(hi)
    {
        dim3 grid(3 * DIM / BN, NTOK / BM);   // (24, 32)
        gemm_qkv<<<grid, 128, GEMM_SMEM>>>(xhi, wqh, qhi, khi, vhi);
    }

    // 2) tensor-core flash attention (fp16 in, fp16 hi out)
    {
        dim3 grid(SEQ / 128, BATCH * HEADS);   // (16, 32)
        attn_mma<<<grid, 256, ATT_SMEM>>>(qhi, khi, vhi, ahi);
    }

    // 3) out = attn_hi @ Wo^T (fp32 out)
    {
        dim3 grid(DIM / BN, NTOK / BM);        // (8, 32)
        gemm_out<<<grid, 128, GEMM_SMEM>>>(ahi, woh, out);
    }
}